// round 8
// baseline (speedup 1.0000x reference)
#include <cuda_runtime.h>
#include <cstdint>

// GeneralizedGraphDiffusion: out = prelu((sum_k theta_k*T_k * a) @ x) @ W^T + b
// N=8192, D=128, K=4.
// R8: warp-specialized pipeline. Warps 8-11 produce (LDG T/a/x -> q build -> smem),
// warps 0-7 consume (mma.sync tf32). Named barriers ready/consumed, 2 stages.
// B read directly from raw row-major x tile (stride 136 -> conflict-free frags).

#define NN 8192
#define DDIM 128
#define BM 64
#define BK 32
#define NT 256
#define TPB 384

#define A0O 0
#define A1O 2304        // A tile = 64*36
#define X0O 4608
#define X1O 8960        // X tile = 32*136 = 4352
#define SMEM_WORDS 13312 // 53248 bytes
#define XSTR 136
#define HS_STRIDE 132

extern __shared__ float sm[];

__device__ __forceinline__ uint32_t tf32r(float f) {
    uint32_t r;
    asm("cvt.rna.tf32.f32 %0, %1;" : "=r"(r) : "f"(f));
    return r;
}
__device__ __forceinline__ void mma8(float* c, uint32_t a0, uint32_t a1,
                                     uint32_t a2, uint32_t a3,
                                     uint32_t b0, uint32_t b1) {
    asm volatile(
        "mma.sync.aligned.m16n8k8.row.col.f32.tf32.tf32.f32 "
        "{%0,%1,%2,%3}, {%4,%5,%6,%7}, {%8,%9}, {%0,%1,%2,%3};"
        : "+f"(c[0]), "+f"(c[1]), "+f"(c[2]), "+f"(c[3])
        : "r"(a0), "r"(a1), "r"(a2), "r"(a3), "r"(b0), "r"(b1));
}
#define BAR_SYNC(id)   asm volatile("bar.sync %0, 384;"   :: "r"(id) : "memory")
#define BAR_ARRIVE(id) asm volatile("bar.arrive %0, 384;" :: "r"(id) : "memory")
#define STS128(ad, x, y, z, w) \
    asm volatile("st.shared.v4.b32 [%0], {%1,%2,%3,%4};" :: \
        "l"(ad), "r"(x), "r"(y), "r"(z), "r"(w) : "memory")

__global__ void ggd_kernel(const float* __restrict__ theta, const float* __restrict__ T,
                           const float* __restrict__ x, const float* __restrict__ a,
                           const float* __restrict__ alpha, const float* __restrict__ W,
                           const float* __restrict__ bias, float* __restrict__ out) {
    const int tid = threadIdx.x;
    const int lane = tid & 31;
    const int wid = tid >> 5;
    const int g = lane >> 2, tig = lane & 3;
    const int i0 = blockIdx.x * BM;
    const size_t slice = (size_t)NN * NN;

    float acc[2][4][4];

    if (wid >= 8) {
        // ================= PRODUCERS (warps 8-11, 128 threads) =================
        const int pid = tid - 256;
        const float th0 = __ldg(theta), th1 = __ldg(theta + 1),
                    th2 = __ldg(theta + 2), th3 = __ldg(theta + 3);
        // A mapping: 4 quads per thread (512 quads = 64 rows x 8 col-quads)
        int stA[4]; size_t gA[4];
#pragma unroll
        for (int q = 0; q < 4; q++) {
            int idx = pid + q * 128;
            int rowA = idx >> 3, cA4 = (idx & 7) * 4;
            stA[q] = rowA * 36 + cA4;
            gA[q] = (size_t)(i0 + rowA) * NN + cA4;
        }
        // X mapping: 8 float4 per thread (1024 = 32 rows x 32 col-quads)
        int xj[8], xc[8];
#pragma unroll
        for (int q = 0; q < 8; q++) {
            int idx = pid + q * 128;
            xj[q] = idx >> 5; xc[q] = (idx & 31) * 4;
        }

        for (int t = 0; t < NT; t++) {
            const int s = t & 1;
            const int J0 = t * BK;
            float4 tA[4][5], xx[8];
#pragma unroll
            for (int q = 0; q < 4; q++) {
                size_t o = gA[q] + (size_t)J0;
                tA[q][0] = *(const float4*)(T + o);
                tA[q][1] = *(const float4*)(T + slice + o);
                tA[q][2] = *(const float4*)(T + 2 * slice + o);
                tA[q][3] = *(const float4*)(T + 3 * slice + o);
                tA[q][4] = *(const float4*)(a + o);
            }
#pragma unroll
            for (int q = 0; q < 8; q++)
                xx[q] = *(const float4*)(x + (size_t)(J0 + xj[q]) * DDIM + xc[q]);

            if (t >= 2) BAR_SYNC(3 + s);          // consumers done with stage s

            float* Ab = sm + (s ? A1O : A0O);
            float* Xb = sm + (s ? X1O : X0O);
#pragma unroll
            for (int q = 0; q < 4; q++) {
                float4 t0 = tA[q][0], t1 = tA[q][1], t2 = tA[q][2], t3 = tA[q][3],
                       av = tA[q][4];
                uint32_t qx = tf32r((th0*t0.x + th1*t1.x + th2*t2.x + th3*t3.x) * av.x);
                uint32_t qy = tf32r((th0*t0.y + th1*t1.y + th2*t2.y + th3*t3.y) * av.y);
                uint32_t qz = tf32r((th0*t0.z + th1*t1.z + th2*t2.z + th3*t3.z) * av.z);
                uint32_t qw = tf32r((th0*t0.w + th1*t1.w + th2*t2.w + th3*t3.w) * av.w);
                STS128((uint32_t*)(Ab + stA[q]), qx, qy, qz, qw);
            }
#pragma unroll
            for (int q = 0; q < 8; q++) {
                uint32_t v0 = tf32r(xx[q].x), v1 = tf32r(xx[q].y),
                         v2 = tf32r(xx[q].z), v3 = tf32r(xx[q].w);
                STS128((uint32_t*)(Xb + xj[q] * XSTR + xc[q]), v0, v1, v2, v3);
            }
            BAR_ARRIVE(1 + s);                    // stage s ready
        }
    } else {
        // ================= CONSUMERS (warps 0-7, 256 threads) =================
        const int wr = wid & 1, wc = wid >> 1;    // 32-row x 32-col warp tile
#pragma unroll
        for (int mi = 0; mi < 2; mi++)
#pragma unroll
            for (int nf = 0; nf < 4; nf++)
#pragma unroll
                for (int e = 0; e < 4; e++) acc[mi][nf][e] = 0.f;

        for (int t = 0; t < NT; t++) {
            const int s = t & 1;
            BAR_SYNC(1 + s);                      // stage s ready
            const uint32_t* As = (const uint32_t*)(sm + (s ? A1O : A0O));
            const uint32_t* Xs = (const uint32_t*)(sm + (s ? X1O : X0O));
#pragma unroll
            for (int ks = 0; ks < 4; ks++) {
                uint32_t af[2][4];
#pragma unroll
                for (int mi = 0; mi < 2; mi++) {
                    const uint32_t* ap = As + (wr*32 + mi*16 + g) * 36 + ks*8 + tig;
                    af[mi][0] = ap[0];
                    af[mi][1] = ap[8 * 36];
                    af[mi][2] = ap[4];
                    af[mi][3] = ap[8 * 36 + 4];
                }
#pragma unroll
                for (int nfl = 0; nfl < 4; nfl++) {
                    const int n = (wc*4 + nfl)*8 + g;
                    uint32_t b0 = Xs[(ks*8 + tig)     * XSTR + n];
                    uint32_t b1 = Xs[(ks*8 + tig + 4) * XSTR + n];
#pragma unroll
                    for (int mi = 0; mi < 2; mi++)
                        mma8(acc[mi][nfl], af[mi][0], af[mi][1], af[mi][2], af[mi][3],
                             b0, b1);
                }
            }
            BAR_ARRIVE(3 + s);                    // stage s consumed
        }
    }

    // ---- epilogue: acc -> hs, prelu + projection (consumers only) ----
    __syncthreads();
    float* hs = sm;   // [64][HS_STRIDE] = 8448 words, overlays stage buffers
    if (tid < 256) {
        const int wr = wid & 1, wc = wid >> 1;
#pragma unroll
        for (int mi = 0; mi < 2; mi++)
#pragma unroll
            for (int nfl = 0; nfl < 4; nfl++) {
                const int col = (wc*4 + nfl)*8 + tig*2;
                const int r0 = wr*32 + mi*16 + g;
                *(float2*)(hs + r0 * HS_STRIDE + col) =
                    make_float2(acc[mi][nfl][0], acc[mi][nfl][1]);
                *(float2*)(hs + (r0 + 8) * HS_STRIDE + col) =
                    make_float2(acc[mi][nfl][2], acc[mi][nfl][3]);
            }
    }
    __syncthreads();
    if (tid < 256) {
        const int tx = tid & 15, ty = tid >> 4;
        const int tx8 = tx * 8, ty4 = ty * 4;
        float oa[4][8];
#pragma unroll
        for (int m = 0; m < 4; m++)
#pragma unroll
            for (int u = 0; u < 8; u++) oa[m][u] = 0.f;

        for (int c4 = 0; c4 < 32; c4++) {
            float4 al = __ldg((const float4*)(alpha + c4 * 4));
            float4 wv[8];
#pragma unroll
            for (int u = 0; u < 8; u++)
                wv[u] = __ldg((const float4*)(W + (size_t)(tx8 + u) * DDIM + c4 * 4));
#pragma unroll
            for (int m = 0; m < 4; m++) {
                float4 hv = *(const float4*)(hs + (ty4 + m) * HS_STRIDE + c4 * 4);
                hv.x = hv.x > 0.f ? hv.x : al.x * hv.x;
                hv.y = hv.y > 0.f ? hv.y : al.y * hv.y;
                hv.z = hv.z > 0.f ? hv.z : al.z * hv.z;
                hv.w = hv.w > 0.f ? hv.w : al.w * hv.w;
#pragma unroll
                for (int u = 0; u < 8; u++)
                    oa[m][u] += hv.x * wv[u].x + hv.y * wv[u].y +
                                hv.z * wv[u].z + hv.w * wv[u].w;
            }
        }
        float4 b0 = __ldg((const float4*)(bias + tx8));
        float4 b1 = __ldg((const float4*)(bias + tx8 + 4));
#pragma unroll
        for (int m = 0; m < 4; m++) {
            size_t go = (size_t)(i0 + ty4 + m) * DDIM;
            *(float4*)(out + go + tx8) =
                make_float4(oa[m][0] + b0.x, oa[m][1] + b0.y,
                            oa[m][2] + b0.z, oa[m][3] + b0.w);
            *(float4*)(out + go + tx8 + 4) =
                make_float4(oa[m][4] + b1.x, oa[m][5] + b1.y,
                            oa[m][6] + b1.z, oa[m][7] + b1.w);
        }
    }
}

extern "C" void kernel_launch(void* const* d_in, const int* in_sizes, int n_in,
                              void* d_out, int out_size) {
    const float* theta = (const float*)d_in[0];
    const float* T     = (const float*)d_in[1];
    const float* x     = (const float*)d_in[2];
    const float* a     = (const float*)d_in[3];
    const float* alpha = (const float*)d_in[4];
    const float* W     = (const float*)d_in[5];
    const float* bias  = (const float*)d_in[6];
    (void)in_sizes; (void)n_in; (void)out_size;

    cudaFuncSetAttribute(ggd_kernel, cudaFuncAttributeMaxDynamicSharedMemorySize,
                         SMEM_WORDS * 4);
    ggd_kernel<<<NN / BM, TPB, SMEM_WORDS * 4>>>(theta, T, x, a, alpha, W, bias,
                                                 (float*)d_out);
}

// round 9
// speedup vs baseline: 1.5245x; 1.5245x over previous
#include <cuda_runtime.h>
#include <cstdint>

// GeneralizedGraphDiffusion: out = prelu((sum_k theta_k*T_k * a) @ x) @ W^T + b
// N=8192, D=128, K=4.
// R9: cp.async 3-stage raw ring (T,a,x) with 2-tile lookahead; build step makes
// q tiles from raw smem (never from registers-in-flight); mma.sync tf32.
// grid 128, BM 64, 8 symmetric warps.

#define NN 8192
#define DDIM 128
#define BM 64
#define BK 32
#define NT 256
#define TPB 256

// smem float offsets
#define TSTG 10240              // per stage: T 4*2048 + a 2048
#define XRAW 30720              // 3 * TSTG
#define XSTG 4352               // [32][136]
#define XSTR 136
#define AOFF 43776              // XRAW + 3*XSTG ; A double buffer 2*2304
#define SMEM_WORDS 48384        // 193536 bytes
#define HS_STRIDE 132

extern __shared__ float sm[];

__device__ __forceinline__ uint32_t tf32r(float f) {
    uint32_t r;
    asm("cvt.rna.tf32.f32 %0, %1;" : "=r"(r) : "f"(f));
    return r;
}
__device__ __forceinline__ void mma8(float* c, uint32_t a0, uint32_t a1,
                                     uint32_t a2, uint32_t a3,
                                     uint32_t b0, uint32_t b1) {
    asm volatile(
        "mma.sync.aligned.m16n8k8.row.col.f32.tf32.tf32.f32 "
        "{%0,%1,%2,%3}, {%4,%5,%6,%7}, {%8,%9}, {%0,%1,%2,%3};"
        : "+f"(c[0]), "+f"(c[1]), "+f"(c[2]), "+f"(c[3])
        : "r"(a0), "r"(a1), "r"(a2), "r"(a3), "r"(b0), "r"(b1));
}
__device__ __forceinline__ void cpa16(uint32_t dst, const float* src) {
    asm volatile("cp.async.cg.shared.global [%0], [%1], 16;" :: "r"(dst), "l"(src));
}
#define CP_COMMIT() asm volatile("cp.async.commit_group;" ::: "memory")
#define CP_WAIT1()  asm volatile("cp.async.wait_group 1;" ::: "memory")
#define STS128(ad, x, y, z, w) \
    asm volatile("st.shared.v4.b32 [%0], {%1,%2,%3,%4};" :: \
        "r"(ad), "r"(x), "r"(y), "r"(z), "r"(w) : "memory")

__global__ __launch_bounds__(TPB, 1)
void ggd_kernel(const float* __restrict__ theta, const float* __restrict__ T,
                const float* __restrict__ x, const float* __restrict__ a,
                const float* __restrict__ alpha, const float* __restrict__ W,
                const float* __restrict__ bias, float* __restrict__ out) {
    const int tid = threadIdx.x;
    const int lane = tid & 31, wid = tid >> 5;
    const int g = lane >> 2, tig = lane & 3;
    const int wr = wid & 1, wc = wid >> 1;
    const int i0 = blockIdx.x * BM;
    const size_t slice = (size_t)NN * NN;

    uint32_t sbase;
    asm("{ .reg .u64 t; cvta.to.shared.u64 t, %1; cvt.u32.u64 %0, t; }"
        : "=r"(sbase) : "l"(sm));

    // ---- cp.async source/dst precompute ----
    // T: 8 chunks/thread (c = tid + q*256, q=0..7); a: 2 chunks; x: 4 chunks.
    const float* srcT[8]; uint32_t dstT[8];
#pragma unroll
    for (int q = 0; q < 8; q++) {
        int c = tid + q * 256;
        int k = c >> 9, rem = c & 511, r = rem >> 3, cc = (rem & 7) * 4;
        srcT[q] = T + (size_t)k * slice + (size_t)(i0 + r) * NN + cc;
        dstT[q] = (uint32_t)c * 16;
    }
    const float* srcA0 = a + (size_t)(i0 + (tid >> 3)) * NN + (tid & 7) * 4;
    const float* srcA1 = srcA0 + (size_t)32 * NN;
    const uint32_t dstA0 = 8192 * 4 + (uint32_t)tid * 16;
    const uint32_t dstA1 = dstA0 + 256 * 16;
    const float* srcX[4]; uint32_t dstX[4];
#pragma unroll
    for (int q = 0; q < 4; q++) {
        int c = tid + q * 256;
        int row = c >> 5, cc = (c & 31) * 4;
        srcX[q] = x + (size_t)row * DDIM + cc;
        dstX[q] = (uint32_t)(row * XSTR + cc) * 4;
    }

#define ISSUE(J0, STG) do {                                                    \
    uint32_t _tb = sbase + (uint32_t)((STG) * TSTG) * 4;                       \
    uint32_t _xb = sbase + (uint32_t)(XRAW + (STG) * XSTG) * 4;                \
    _Pragma("unroll") for (int _q = 0; _q < 8; _q++)                           \
        cpa16(_tb + dstT[_q], srcT[_q] + (J0));                                \
    cpa16(_tb + dstA0, srcA0 + (J0));                                          \
    cpa16(_tb + dstA1, srcA1 + (J0));                                          \
    _Pragma("unroll") for (int _q = 0; _q < 4; _q++)                           \
        cpa16(_xb + dstX[_q], srcX[_q] + (size_t)(J0) * DDIM);                 \
} while (0)

    const float th0 = __ldg(theta), th1 = __ldg(theta + 1),
                th2 = __ldg(theta + 2), th3 = __ldg(theta + 3);

    float acc[2][4][4];
#pragma unroll
    for (int mi = 0; mi < 2; mi++)
#pragma unroll
        for (int nf = 0; nf < 4; nf++)
#pragma unroll
            for (int e = 0; e < 4; e++) acc[mi][nf][e] = 0.f;

    // prologue: tiles 0 and 1 in flight
    ISSUE(0, 0);  CP_COMMIT();
    ISSUE(BK, 1); CP_COMMIT();

    int s3 = 0;   // t % 3
    for (int t = 0; t < NT; t++) {
        CP_WAIT1();            // group t complete
        __syncthreads();       // arrivals visible; t-1's reads all done

        // issue tile t+2 into slot (t+2)%3 == (t-1)%3 (freed by the barrier)
        if (t + 2 < NT) {
            int stg = s3 + 2; if (stg >= 3) stg -= 3;
            ISSUE((t + 2) * BK, stg);
        }
        CP_COMMIT();           // one group per iteration (possibly empty)

        // ---- build: q -> A[t&1]; cvt x in place ----
        const float* traw = sm + s3 * TSTG;
        const float* araw = traw + 8192;
        float* Xb = sm + XRAW + s3 * XSTG;
        uint32_t Abad = sbase + (uint32_t)(AOFF + (t & 1) * 2304) * 4;
#pragma unroll
        for (int qq = 0; qq < 2; qq++) {
            int idx = tid + qq * 256;
            int row = idx >> 3, c4 = (idx & 7) * 4;
            float4 t0 = *(const float4*)(traw + row * 32 + c4);
            float4 t1 = *(const float4*)(traw + 2048 + row * 32 + c4);
            float4 t2 = *(const float4*)(traw + 4096 + row * 32 + c4);
            float4 t3 = *(const float4*)(traw + 6144 + row * 32 + c4);
            float4 av = *(const float4*)(araw + row * 32 + c4);
            uint32_t qx = tf32r((th0*t0.x + th1*t1.x + th2*t2.x + th3*t3.x) * av.x);
            uint32_t qy = tf32r((th0*t0.y + th1*t1.y + th2*t2.y + th3*t3.y) * av.y);
            uint32_t qz = tf32r((th0*t0.z + th1*t1.z + th2*t2.z + th3*t3.z) * av.z);
            uint32_t qw = tf32r((th0*t0.w + th1*t1.w + th2*t2.w + th3*t3.w) * av.w);
            STS128(Abad + (uint32_t)(row * 36 + c4) * 4, qx, qy, qz, qw);
        }
#pragma unroll
        for (int qq = 0; qq < 4; qq++) {
            int idx = tid + qq * 256;
            float* p = Xb + (idx >> 5) * XSTR + (idx & 31) * 4;
            float4 v = *(const float4*)p;
            uint32_t pa;
            asm("{ .reg .u64 t; cvta.to.shared.u64 t, %1; cvt.u32.u64 %0, t; }"
                : "=r"(pa) : "l"(p));
            STS128(pa, tf32r(v.x), tf32r(v.y), tf32r(v.z), tf32r(v.w));
        }
        __syncthreads();       // A + converted X visible

        // ---- mma ----
        const uint32_t* As = (const uint32_t*)(sm + AOFF + (t & 1) * 2304);
        const uint32_t* Xs = (const uint32_t*)Xb;
#pragma unroll
        for (int ks = 0; ks < 4; ks++) {
            uint32_t af[2][4];
#pragma unroll
            for (int mi = 0; mi < 2; mi++) {
                const uint32_t* ap = As + (wr*32 + mi*16 + g) * 36 + ks*8 + tig;
                af[mi][0] = ap[0];
                af[mi][1] = ap[8 * 36];
                af[mi][2] = ap[4];
                af[mi][3] = ap[8 * 36 + 4];
            }
#pragma unroll
            for (int nfl = 0; nfl < 4; nfl++) {
                const int n = (wc*4 + nfl)*8 + g;
                uint32_t b0 = Xs[(ks*8 + tig)     * XSTR + n];
                uint32_t b1 = Xs[(ks*8 + tig + 4) * XSTR + n];
#pragma unroll
                for (int mi = 0; mi < 2; mi++)
                    mma8(acc[mi][nfl], af[mi][0], af[mi][1], af[mi][2], af[mi][3],
                         b0, b1);
            }
        }
        if (++s3 == 3) s3 = 0;
    }

    // ---- epilogue: acc -> hs, prelu + projection ----
    __syncthreads();
    float* hs = sm;   // [64][HS_STRIDE]
#pragma unroll
    for (int mi = 0; mi < 2; mi++)
#pragma unroll
        for (int nfl = 0; nfl < 4; nfl++) {
            const int col = (wc*4 + nfl)*8 + tig*2;
            const int r0 = wr*32 + mi*16 + g;
            *(float2*)(hs + r0 * HS_STRIDE + col) =
                make_float2(acc[mi][nfl][0], acc[mi][nfl][1]);
            *(float2*)(hs + (r0 + 8) * HS_STRIDE + col) =
                make_float2(acc[mi][nfl][2], acc[mi][nfl][3]);
        }
    __syncthreads();

    const int tx = tid & 15, ty = tid >> 4;
    const int tx8 = tx * 8, ty4 = ty * 4;
    float oa[4][8];
#pragma unroll
    for (int m = 0; m < 4; m++)
#pragma unroll
        for (int u = 0; u < 8; u++) oa[m][u] = 0.f;

    for (int c4 = 0; c4 < 32; c4++) {
        float4 al = __ldg((const float4*)(alpha + c4 * 4));
        float4 wv[8];
#pragma unroll
        for (int u = 0; u < 8; u++)
            wv[u] = __ldg((const float4*)(W + (size_t)(tx8 + u) * DDIM + c4 * 4));
#pragma unroll
        for (int m = 0; m < 4; m++) {
            float4 hv = *(const float4*)(hs + (ty4 + m) * HS_STRIDE + c4 * 4);
            hv.x = hv.x > 0.f ? hv.x : al.x * hv.x;
            hv.y = hv.y > 0.f ? hv.y : al.y * hv.y;
            hv.z = hv.z > 0.f ? hv.z : al.z * hv.z;
            hv.w = hv.w > 0.f ? hv.w : al.w * hv.w;
#pragma unroll
            for (int u = 0; u < 8; u++)
                oa[m][u] += hv.x * wv[u].x + hv.y * wv[u].y +
                            hv.z * wv[u].z + hv.w * wv[u].w;
        }
    }
    float4 b0 = __ldg((const float4*)(bias + tx8));
    float4 b1 = __ldg((const float4*)(bias + tx8 + 4));
#pragma unroll
    for (int m = 0; m < 4; m++) {
        size_t go = (size_t)(i0 + ty4 + m) * DDIM;
        *(float4*)(out + go + tx8) =
            make_float4(oa[m][0] + b0.x, oa[m][1] + b0.y,
                        oa[m][2] + b0.z, oa[m][3] + b0.w);
        *(float4*)(out + go + tx8 + 4) =
            make_float4(oa[m][4] + b1.x, oa[m][5] + b1.y,
                        oa[m][6] + b1.z, oa[m][7] + b1.w);
    }
}

extern "C" void kernel_launch(void* const* d_in, const int* in_sizes, int n_in,
                              void* d_out, int out_size) {
    const float* theta = (const float*)d_in[0];
    const float* T     = (const float*)d_in[1];
    const float* x     = (const float*)d_in[2];
    const float* a     = (const float*)d_in[3];
    const float* alpha = (const float*)d_in[4];
    const float* W     = (const float*)d_in[5];
    const float* bias  = (const float*)d_in[6];
    (void)in_sizes; (void)n_in; (void)out_size;

    cudaFuncSetAttribute(ggd_kernel, cudaFuncAttributeMaxDynamicSharedMemorySize,
                         SMEM_WORDS * 4);
    ggd_kernel<<<NN / BM, TPB, SMEM_WORDS * 4>>>(theta, T, x, a, alpha, W, bias,
                                                 (float*)d_out);
}